// round 5
// baseline (speedup 1.0000x reference)
#include <cuda_runtime.h>
#include <math.h>

#define DIM 1024
#define MAX_ROWS 32768

// Scratch (static __device__ arrays: allocation-free, harness-legal)
__device__ int4 g_stats[MAX_ROWS];   // {mean, inv, ts, 0} per row
__device__ int4 g_wb[DIM / 4];       // packed int16 {w0|w1, w2|w3, b0|b1, b2|b3} per col-quad

// ---------------- K1: per-row statistics (pure read stream) ----------------
__global__ __launch_bounds__(256)
void iln_stats(const float* __restrict__ x,
               const float* __restrict__ weight,
               const float* __restrict__ bias,
               int n_rows)
{
    __shared__ int s_lut[32];
    const int tid = threadIdx.x;

    // 32-entry isqrt LUT, exact: round((1<<15)/sqrt(2^parity*(1+m/16)))
    if (tid < 32) {
        const int parity = tid >> 4;
        const int mant = tid & 15;
        const double val = (double)(1 << parity) * (1.0 + (double)mant * 0.0625);
        s_lut[tid] = (int)llrint(32768.0 / sqrt(val));
    }

    // Block 0 additionally packs quantized weight/bias for K2 (once).
    if (blockIdx.x == 0) {
        const float4 w4 = ((const float4*)weight)[tid];
        const float4 b4 = ((const float4*)bias)[tid];
        const int w0 = __float2int_rn(w4.x * 256.0f);
        const int w1 = __float2int_rn(w4.y * 256.0f);
        const int w2 = __float2int_rn(w4.z * 256.0f);
        const int w3 = __float2int_rn(w4.w * 256.0f);
        const int b0 = __float2int_rn(b4.x * 256.0f);
        const int b1 = __float2int_rn(b4.y * 256.0f);
        const int b2 = __float2int_rn(b4.z * 256.0f);
        const int b3 = __float2int_rn(b4.w * 256.0f);
        g_wb[tid] = make_int4((w0 & 0xffff) | (w1 << 16),
                              (w2 & 0xffff) | (w3 << 16),
                              (b0 & 0xffff) | (b1 << 16),
                              (b2 & 0xffff) | (b3 << 16));
    }
    __syncthreads();

    const int warp = tid >> 5;
    const int lane = tid & 31;
    const int row = blockIdx.x * 8 + warp;
    if (row >= n_rows) return;

    const float4* __restrict__ xr = (const float4*)(x + (size_t)row * DIM);

    // Front-batched loads: 8 independent LDG.128
    float4 v[8];
    #pragma unroll
    for (int j = 0; j < 8; j++) v[j] = xr[j * 32 + lane];

    int sum = 0, sumsq = 0;   // sumsq max ~1e8 << 2^31, exact
    #pragma unroll
    for (int j = 0; j < 8; j++) {
        const int a = __float2int_rn(v[j].x);
        const int b = __float2int_rn(v[j].y);
        const int c = __float2int_rn(v[j].z);
        const int d = __float2int_rn(v[j].w);
        sum   += a + b + c + d;
        sumsq += a * a + b * b + c * c + d * d;
    }
    sum   = __reduce_add_sync(0xffffffffu, sum);
    sumsq = __reduce_add_sync(0xffffffffu, sumsq);

    if (lane == 0) {
        const int mean = (sum * 64) >> 16;                 // fixed-point mean
        const long long ssy = (long long)sumsq
                            - 2LL * (long long)mean * (long long)sum
                            + (long long)DIM * (long long)mean * (long long)mean;
        long long var = (ssy * 64) >> 16;
        if (var < 1) var = 1;
        const int k = 63 - __clzll((unsigned long long)var);  // floor(log2), exact
        const int sa = k - 4;
        const int mant = (sa >= 0) ? (int)((var >> sa) & 15)
                                   : (int)((var << (-sa)) & 15);
        const int inv = s_lut[((k & 1) << 4) | mant];
        const int ts = (k >> 1) + 15;                      // p + SHIFT(0) + Q_LUT(15)
        g_stats[row] = make_int4(mean, inv, ts, 0);
    }
}

// ---------------- K2: apply (pure map, 2 rows per block) ----------------
__device__ __forceinline__ float4 apply_quad(float4 v, int mean, int inv, int ts,
                                             int w01, int w23, int b01, int b23)
{
    const int w0 = (w01 << 16) >> 16, w1 = w01 >> 16;
    const int w2 = (w23 << 16) >> 16, w3 = w23 >> 16;
    const int b0 = (b01 << 16) >> 16, b1 = b01 >> 16;
    const int b2 = (b23 << 16) >> 16, b3 = b23 >> 16;
    float4 o;
    long long t;
    t = (((long long)((__float2int_rn(v.x) - mean) * inv) * (long long)w0) >> ts) + b0;
    o.x = (float)t * 0.00390625f;
    t = (((long long)((__float2int_rn(v.y) - mean) * inv) * (long long)w1) >> ts) + b1;
    o.y = (float)t * 0.00390625f;
    t = (((long long)((__float2int_rn(v.z) - mean) * inv) * (long long)w2) >> ts) + b2;
    o.z = (float)t * 0.00390625f;
    t = (((long long)((__float2int_rn(v.w) - mean) * inv) * (long long)w3) >> ts) + b3;
    o.w = (float)t * 0.00390625f;
    return o;
}

__global__ __launch_bounds__(256)
void iln_apply(const float* __restrict__ x,
               float* __restrict__ out,
               int n_rows)
{
    const int tid = threadIdx.x;
    const int row0 = blockIdx.x * 2;
    const int row1 = row0 + 1;
    const bool has1 = (row1 < n_rows);

    // Thread tid always owns column-quad tid (rows are 256 quads wide).
    const int4 wb = g_wb[tid];

    const float4* __restrict__ x0 = (const float4*)(x + (size_t)row0 * DIM);
    const float4* __restrict__ x1 = (const float4*)(x + (size_t)row1 * DIM);

    // Issue all loads up front (independent)
    const float4 v0 = x0[tid];
    float4 v1;
    if (has1) v1 = x1[tid];
    const int4 st0 = g_stats[row0];                 // uniform within block
    int4 st1;
    if (has1) st1 = g_stats[row1];

    float4* __restrict__ o0 = (float4*)(out + (size_t)row0 * DIM);
    o0[tid] = apply_quad(v0, st0.x, st0.y, st0.z, wb.x, wb.y, wb.z, wb.w);

    if (has1) {
        float4* __restrict__ o1 = (float4*)(out + (size_t)row1 * DIM);
        o1[tid] = apply_quad(v1, st1.x, st1.y, st1.z, wb.x, wb.y, wb.z, wb.w);
    }
}

extern "C" void kernel_launch(void* const* d_in, const int* in_sizes, int n_in,
                              void* d_out, int out_size) {
    const float* x      = (const float*)d_in[0];
    const float* weight = (const float*)d_in[1];
    const float* bias   = (const float*)d_in[2];
    // d_in[3] (isqrt_lut) intentionally unused: LUT recomputed exactly in-kernel.
    float* out = (float*)d_out;

    const int n_rows = in_sizes[0] / DIM;

    const int blocks1 = (n_rows + 7) / 8;           // 8 rows (warps) per block
    iln_stats<<<blocks1, 256>>>(x, weight, bias, n_rows);

    const int blocks2 = (n_rows + 1) / 2;           // 2 rows per block
    iln_apply<<<blocks2, 256>>>(x, out, n_rows);
}